// round 3
// baseline (speedup 1.0000x reference)
#include <cuda_runtime.h>
#include <cstdint>

// Problem: out[B,10] = x[B,64] @ W[64,10], fp32. B = 2,097,152.
// Pure HBM-streaming kernel: 512MB x read + 80MB out write, W tiny (kept in SMEM,
// transposed so k-consecutive pairs are contiguous for f32x2 packed FMA).
// One thread = one row. 128-bit streaming loads; fma.rn.f32x2 halves FMA issue count.

#define BATCH (2097152)
#define IN_DIM 64
#define OUT_DIM 10
#define BLOCK 256

__device__ __forceinline__ void ffma2(uint64_t& d, uint64_t a, uint64_t b) {
    // packed 2xFP32 FMA: d = a*b + d  (element-wise on the two f32 halves)
    asm volatile("fma.rn.f32x2 %0, %1, %2, %0;" : "+l"(d) : "l"(a), "l"(b));
}

__global__ void __launch_bounds__(BLOCK) neat_matmul_kernel(
    const float* __restrict__ x,
    const float* __restrict__ W,
    float* __restrict__ out)
{
    // WT[j][k] = W[k][j]; row j is 64 contiguous floats -> LDS.128 gives
    // two (w[k],w[k+1]) f32x2 pairs at once. All lanes read the same address
    // (broadcast, conflict-free).
    __shared__ float WT[OUT_DIM][IN_DIM];

    for (int t = threadIdx.x; t < IN_DIM * OUT_DIM; t += BLOCK) {
        int k = t / OUT_DIM;
        int j = t % OUT_DIM;
        WT[j][k] = W[t];
    }
    __syncthreads();

    const int row = blockIdx.x * BLOCK + threadIdx.x;  // grid exactly covers BATCH

    // x row: 64 floats = 256B, 16-byte aligned. Load as uint4 (LDG.128 .cs),
    // reinterpret each 16B as two packed f32x2 operands (little-endian: free).
    const uint4* __restrict__ xr =
        reinterpret_cast<const uint4*>(x) + (size_t)row * (IN_DIM / 4);

    uint64_t acc[OUT_DIM];
#pragma unroll
    for (int j = 0; j < OUT_DIM; ++j) acc[j] = 0ull;

#pragma unroll 4
    for (int c = 0; c < IN_DIM / 4; ++c) {
        uint4 xv = __ldcs(xr + c);
        uint64_t x01 = (uint64_t)xv.x | ((uint64_t)xv.y << 32);  // (x[4c],   x[4c+1])
        uint64_t x23 = (uint64_t)xv.z | ((uint64_t)xv.w << 32);  // (x[4c+2], x[4c+3])
#pragma unroll
        for (int j = 0; j < OUT_DIM; ++j) {
            const ulonglong2 wv =
                *reinterpret_cast<const ulonglong2*>(&WT[j][c * 4]);  // LDS.128 broadcast
            ffma2(acc[j], x01, wv.x);
            ffma2(acc[j], x23, wv.y);
        }
    }

    // Horizontal add of the two f32 halves of each accumulator.
    float s[OUT_DIM];
#pragma unroll
    for (int j = 0; j < OUT_DIM; ++j) {
        float lo = __uint_as_float((uint32_t)(acc[j] & 0xFFFFFFFFull));
        float hi = __uint_as_float((uint32_t)(acc[j] >> 32));
        s[j] = lo + hi;
    }

    // out row = 10 floats = 40B, 8-byte aligned -> 5x STG.64 streaming.
    float2* __restrict__ o = reinterpret_cast<float2*>(out + (size_t)row * OUT_DIM);
    __stcs(o + 0, make_float2(s[0], s[1]));
    __stcs(o + 1, make_float2(s[2], s[3]));
    __stcs(o + 2, make_float2(s[4], s[5]));
    __stcs(o + 3, make_float2(s[6], s[7]));
    __stcs(o + 4, make_float2(s[8], s[9]));
}

extern "C" void kernel_launch(void* const* d_in, const int* in_sizes, int n_in,
                              void* d_out, int out_size) {
    const float* x = (const float*)d_in[0];  // [BATCH, 64]
    const float* W = (const float*)d_in[1];  // [64, 10]
    float* out = (float*)d_out;              // [BATCH, 10]

    const int grid = BATCH / BLOCK;  // 8192, exact
    neat_matmul_kernel<<<grid, BLOCK>>>(x, W, out);
}

// round 4
// speedup vs baseline: 1.0218x; 1.0218x over previous
#include <cuda_runtime.h>
#include <cstdint>

// out[B,10] = x[B,64] @ W[64,10], fp32, B = 2,097,152.
// R3: L1/shared-crossbar was the R2 bottleneck (92.3% L1, 160 LDS.128/row).
// Fix: (a) 4 rows per thread, block-strided (coalesced LDG), so each W
// shared-load feeds 4 rows; (b) output-pair-packed f32x2 accumulators so the
// warp reads only 40B of W per k (W stays row-major: W[k][2p],W[k][2p+1] are
// contiguous) and results store directly with no horizontal reduction.

#define BATCH   2097152
#define IN_DIM  64
#define OUT_DIM 10
#define BLOCK   256
#define RPT     4                       // rows per thread
#define ROWS_PER_BLOCK (BLOCK * RPT)    // 1024

__device__ __forceinline__ void ffma2(uint64_t& d, uint64_t a, uint64_t b) {
    asm volatile("fma.rn.f32x2 %0, %1, %2, %0;" : "+l"(d) : "l"(a), "l"(b));
}

__device__ __forceinline__ uint64_t dup2(float v) {
    uint64_t d;
    asm("mov.b64 %0, {%1, %1};" : "=l"(d) : "f"(v));
    return d;
}

__global__ void __launch_bounds__(BLOCK) neat_matmul_kernel(
    const float* __restrict__ x,
    const float* __restrict__ W,
    float* __restrict__ out)
{
    // Ws[k][p] = (W[k][2p], W[k][2p+1]) packed as u64.
    // Row stride padded to 6 u64 (48B) so the p=0..3 pairs are 16B-aligned
    // for LDS.128.
    __shared__ alignas(16) uint64_t Ws[IN_DIM][6];

    for (int t = threadIdx.x; t < IN_DIM * 5; t += BLOCK) {
        int k = t / 5, p = t % 5;
        float lo = W[k * OUT_DIM + 2 * p];
        float hi = W[k * OUT_DIM + 2 * p + 1];
        uint64_t v;
        asm("mov.b64 %0, {%1, %2};" : "=l"(v) : "f"(lo), "f"(hi));
        Ws[k][p] = v;
    }
    __syncthreads();

    // Block-strided row assignment: row r = blockBase + r*BLOCK + tid,
    // so every LDG across the warp is consecutive 16B -> fully coalesced.
    const size_t blockBase = (size_t)blockIdx.x * ROWS_PER_BLOCK + threadIdx.x;

    const float4* __restrict__ xr[RPT];
#pragma unroll
    for (int r = 0; r < RPT; ++r)
        xr[r] = reinterpret_cast<const float4*>(x) +
                (blockBase + (size_t)r * BLOCK) * (IN_DIM / 4);

    // acc[r][p] = (out[2p], out[2p+1]) for row r, packed f32x2.
    uint64_t acc[RPT][5];
#pragma unroll
    for (int r = 0; r < RPT; ++r)
#pragma unroll
        for (int p = 0; p < 5; ++p) acc[r][p] = 0ull;

#pragma unroll 2
    for (int c = 0; c < IN_DIM / 4; ++c) {
        float4 xv[RPT];
#pragma unroll
        for (int r = 0; r < RPT; ++r)
            xv[r] = __ldcs(xr[r] + c);     // 4 independent LDG.128 -> MLP>=4

#pragma unroll
        for (int q = 0; q < 4; ++q) {
            const int k = 4 * c + q;
            // 40B of W for this k, shared by all 4 rows:
            const ulonglong2 w01 = *reinterpret_cast<const ulonglong2*>(&Ws[k][0]);
            const ulonglong2 w23 = *reinterpret_cast<const ulonglong2*>(&Ws[k][2]);
            const uint64_t   w4  = Ws[k][4];
#pragma unroll
            for (int r = 0; r < RPT; ++r) {
                const float xk = (q == 0) ? xv[r].x :
                                 (q == 1) ? xv[r].y :
                                 (q == 2) ? xv[r].z : xv[r].w;
                const uint64_t xx = dup2(xk);
                ffma2(acc[r][0], xx, w01.x);
                ffma2(acc[r][1], xx, w01.y);
                ffma2(acc[r][2], xx, w23.x);
                ffma2(acc[r][3], xx, w23.y);
                ffma2(acc[r][4], xx, w4);
            }
        }
    }

    // Each acc pair is already (out[2p], out[2p+1]) -> direct 8B streaming
    // stores, no horizontal reduction. Row = 40B, 8B-aligned.
#pragma unroll
    for (int r = 0; r < RPT; ++r) {
        unsigned long long* __restrict__ o =
            reinterpret_cast<unsigned long long*>(
                out + (blockBase + (size_t)r * BLOCK) * OUT_DIM);
#pragma unroll
        for (int p = 0; p < 5; ++p)
            __stcs(o + p, (unsigned long long)acc[r][p]);
    }
}

extern "C" void kernel_launch(void* const* d_in, const int* in_sizes, int n_in,
                              void* d_out, int out_size) {
    const float* x = (const float*)d_in[0];  // [BATCH, 64]
    const float* W = (const float*)d_in[1];  // [64, 10] row-major
    float* out = (float*)d_out;              // [BATCH, 10]

    const int grid = BATCH / ROWS_PER_BLOCK; // 2048, exact
    neat_matmul_kernel<<<grid, BLOCK>>>(x, W, out);
}

// round 5
// speedup vs baseline: 1.1932x; 1.1678x over previous
#include <cuda_runtime.h>
#include <cstdint>

// out[B,10] = x[B,64] @ W[64,10], fp32, B = 2,097,152.
// R4: R3 was latency-bound (no pipe >70%, DRAM 42%): loads were bursty
// (8 in flight, then a 400-cyc FFMA phase with 0 outstanding). Fix = register
// software pipeline (PF=2 chunk double-buffer) so every warp keeps 8 LDG.128
// in flight continuously; launch_bounds(256,2) keeps >=16 warps/SM.

#define BATCH   2097152
#define IN_DIM  64
#define OUT_DIM 10
#define BLOCK   256
#define RPT     4                       // rows per thread (block-strided)
#define PF      2                       // prefetch depth in chunks
#define ROWS_PER_BLOCK (BLOCK * RPT)    // 1024
#define NCHUNK  (IN_DIM / 4)            // 16 float4 chunks per row

__device__ __forceinline__ void ffma2(uint64_t& d, uint64_t a, uint64_t b) {
    asm volatile("fma.rn.f32x2 %0, %1, %2, %0;" : "+l"(d) : "l"(a), "l"(b));
}

__device__ __forceinline__ uint64_t dup2(float v) {
    uint64_t d;
    asm("mov.b64 %0, {%1, %1};" : "=l"(d) : "f"(v));
    return d;
}

__global__ void __launch_bounds__(BLOCK, 2) neat_matmul_kernel(
    const float* __restrict__ x,
    const float* __restrict__ W,
    float* __restrict__ out)
{
    // Ws[k][p] = (W[k][2p], W[k][2p+1]) packed u64; row padded to 48B so
    // p=0..3 are LDS.128-able.
    __shared__ alignas(16) uint64_t Ws[IN_DIM][6];

    for (int t = threadIdx.x; t < IN_DIM * 5; t += BLOCK) {
        int k = t / 5, p = t % 5;
        uint64_t v;
        asm("mov.b64 %0, {%1, %2};" : "=l"(v)
            : "f"(W[k * OUT_DIM + 2 * p]), "f"(W[k * OUT_DIM + 2 * p + 1]));
        Ws[k][p] = v;
    }
    __syncthreads();

    // Block-strided rows: row_r = base + r*BLOCK  -> warp LDGs fully coalesced.
    // Single base pointer; r,c become immediate offsets (r*4096 float4s, c).
    const size_t base = (size_t)blockIdx.x * ROWS_PER_BLOCK + threadIdx.x;
    const float4* __restrict__ xb =
        reinterpret_cast<const float4*>(x) + base * (IN_DIM / 4);

    uint64_t acc[RPT][5];
#pragma unroll
    for (int r = 0; r < RPT; ++r)
#pragma unroll
        for (int p = 0; p < 5; ++p) acc[r][p] = 0ull;

    // Prime the pipeline: chunks 0..PF-1 in flight.
    float4 buf[PF][RPT];
#pragma unroll
    for (int s = 0; s < PF; ++s)
#pragma unroll
        for (int r = 0; r < RPT; ++r)
            buf[s][r] = __ldcs(xb + (size_t)r * BLOCK * (IN_DIM / 4) + s);

#pragma unroll
    for (int c = 0; c < NCHUNK; ++c) {
        float4 xv[RPT];
#pragma unroll
        for (int r = 0; r < RPT; ++r) xv[r] = buf[c % PF][r];

        // Refill this slot BEFORE compute -> loads always outstanding.
        if (c + PF < NCHUNK) {
#pragma unroll
            for (int r = 0; r < RPT; ++r)
                buf[c % PF][r] =
                    __ldcs(xb + (size_t)r * BLOCK * (IN_DIM / 4) + c + PF);
        }

#pragma unroll
        for (int q = 0; q < 4; ++q) {
            const int k = 4 * c + q;
            const ulonglong2 w01 = *reinterpret_cast<const ulonglong2*>(&Ws[k][0]);
            const ulonglong2 w23 = *reinterpret_cast<const ulonglong2*>(&Ws[k][2]);
            const uint64_t   w4  = Ws[k][4];
#pragma unroll
            for (int r = 0; r < RPT; ++r) {
                const float xk = (q == 0) ? xv[r].x :
                                 (q == 1) ? xv[r].y :
                                 (q == 2) ? xv[r].z : xv[r].w;
                const uint64_t xx = dup2(xk);
                ffma2(acc[r][0], xx, w01.x);
                ffma2(acc[r][1], xx, w01.y);
                ffma2(acc[r][2], xx, w23.x);
                ffma2(acc[r][3], xx, w23.y);
                ffma2(acc[r][4], xx, w4);
            }
        }
    }

    // acc pairs are already (out[2p], out[2p+1]) -> 5 x STG.64 per row.
#pragma unroll
    for (int r = 0; r < RPT; ++r) {
        unsigned long long* __restrict__ o =
            reinterpret_cast<unsigned long long*>(
                out + (base + (size_t)r * BLOCK) * OUT_DIM);
#pragma unroll
        for (int p = 0; p < 5; ++p)
            __stcs(o + p, (unsigned long long)acc[r][p]);
    }
}

extern "C" void kernel_launch(void* const* d_in, const int* in_sizes, int n_in,
                              void* d_out, int out_size) {
    const float* x = (const float*)d_in[0];  // [BATCH, 64]
    const float* W = (const float*)d_in[1];  // [64, 10] row-major
    float* out = (float*)d_out;              // [BATCH, 10]

    const int grid = BATCH / ROWS_PER_BLOCK; // 2048, exact
    neat_matmul_kernel<<<grid, BLOCK>>>(x, W, out);
}

// round 6
// speedup vs baseline: 1.3396x; 1.1227x over previous
#include <cuda_runtime.h>
#include <cstdint>

// out[B,10] = x[B,64] @ W[64,10], fp32, B = 2,097,152.
// R5: register pipelining capped at 45% DRAM (PF limited by regfile, occ 23%).
// Fix: cp.async.cg double-buffered smem staging -> 128KB in flight per SM,
// decoupled from registers. RPT=8 halves W shared traffic; 80B-padded rows
// (5 granules, gcd(5,8)=1) make all LDS.128 conflict-free.

#define BATCH     2097152
#define IN_DIM    64
#define OUT_DIM   10
#define BLOCK     128
#define RPT       8
#define TILE_ROWS (BLOCK * RPT)              // 1024 rows per block
#define KSTAGES   4                          // 4 x 16 floats = 64 k
#define ROW_STRIDE 80                        // 64B data + 16B pad
#define STAGE_BYTES (TILE_ROWS * ROW_STRIDE) // 81920
#define W_OFF     (2 * STAGE_BYTES)          // 163840
#define SMEM_TOTAL (W_OFF + IN_DIM * 48)     // 166912 bytes

__device__ __forceinline__ void ffma2(uint64_t& d, uint64_t a, uint64_t b) {
    asm volatile("fma.rn.f32x2 %0, %1, %2, %0;" : "+l"(d) : "l"(a), "l"(b));
}

__device__ __forceinline__ uint64_t dup2(float v) {
    uint64_t d;
    asm("mov.b64 %0, {%1, %1};" : "=l"(d) : "f"(v));
    return d;
}

__global__ void __launch_bounds__(BLOCK) neat_matmul_kernel(
    const float* __restrict__ x,
    const float* __restrict__ W,
    float* __restrict__ out)
{
    extern __shared__ __align__(128) unsigned char smem[];
    const int tid = threadIdx.x;
    const size_t tileBase = (size_t)blockIdx.x * TILE_ROWS;

    // Stage W: Ws[k][p] = (W[k][2p], W[k][2p+1]) packed u64, row padded to 48B.
    {
        uint64_t* Ws = reinterpret_cast<uint64_t*>(smem + W_OFF);
        for (int t = tid; t < IN_DIM * 5; t += BLOCK) {
            int k = t / 5, p = t % 5;
            uint64_t v;
            asm("mov.b64 %0, {%1, %2};" : "=l"(v)
                : "f"(W[k * OUT_DIM + 2 * p]), "f"(W[k * OUT_DIM + 2 * p + 1]));
            Ws[k * 6 + p] = v;
        }
    }

    const char* xbase = reinterpret_cast<const char*>(x) + tileBase * (IN_DIM * 4);

    // Issue one k-stage (1024 rows x 64B) into buffer s&1: 32 cp.async per thread.
    // Lanes fetch consecutive 16B granules -> coalesced global; dst granule
    // pattern = r*5 + c (mod 8) -> near-uniform STS banks.
    auto issue = [&](int s) {
        unsigned dstbase =
            (unsigned)__cvta_generic_to_shared(smem + (size_t)(s & 1) * STAGE_BYTES);
#pragma unroll
        for (int i = 0; i < 32; ++i) {
            int g = tid + i * BLOCK;          // 0..4095
            int r = g >> 2, c = g & 3;
            const char* src = xbase + r * 256 + s * 64 + c * 16;
            unsigned dst = dstbase + r * ROW_STRIDE + c * 16;
            asm volatile("cp.async.cg.shared.global [%0], [%1], 16;"
                         :: "r"(dst), "l"(src) : "memory");
        }
        asm volatile("cp.async.commit_group;" ::: "memory");
    };

    issue(0);
    issue(1);

    uint64_t acc[RPT][5];
#pragma unroll
    for (int j = 0; j < RPT; ++j)
#pragma unroll
        for (int p = 0; p < 5; ++p) acc[j][p] = 0ull;

    const uint64_t* Ws = reinterpret_cast<const uint64_t*>(smem + W_OFF);

#pragma unroll
    for (int s = 0; s < KSTAGES; ++s) {
        // gs must be complete; groups issued after s: min(1, KSTAGES-1-s).
        if (s < KSTAGES - 1)
            asm volatile("cp.async.wait_group 1;" ::: "memory");
        else
            asm volatile("cp.async.wait_group 0;" ::: "memory");
        __syncthreads();

        const unsigned char* buf = smem + (size_t)(s & 1) * STAGE_BYTES;

#pragma unroll
        for (int c = 0; c < 4; ++c) {
            float4 xv[RPT];
#pragma unroll
            for (int j = 0; j < RPT; ++j)
                xv[j] = *reinterpret_cast<const float4*>(
                    buf + (tid + j * BLOCK) * ROW_STRIDE + c * 16);

#pragma unroll
            for (int q = 0; q < 4; ++q) {
                const int k = s * 16 + c * 4 + q;
                const ulonglong2 w01 =
                    *reinterpret_cast<const ulonglong2*>(Ws + k * 6);
                const ulonglong2 w23 =
                    *reinterpret_cast<const ulonglong2*>(Ws + k * 6 + 2);
                const uint64_t w4 = Ws[k * 6 + 4];
#pragma unroll
                for (int j = 0; j < RPT; ++j) {
                    const float xk = (q == 0) ? xv[j].x :
                                     (q == 1) ? xv[j].y :
                                     (q == 2) ? xv[j].z : xv[j].w;
                    const uint64_t xx = dup2(xk);
                    ffma2(acc[j][0], xx, w01.x);
                    ffma2(acc[j][1], xx, w01.y);
                    ffma2(acc[j][2], xx, w23.x);
                    ffma2(acc[j][3], xx, w23.y);
                    ffma2(acc[j][4], xx, w4);
                }
            }
        }

        __syncthreads();                 // everyone done reading buf s&1
        if (s + 2 < KSTAGES) issue(s + 2);
    }

    // acc pairs are (out[2p], out[2p+1]) -> direct streaming STG.64, no reduce.
#pragma unroll
    for (int j = 0; j < RPT; ++j) {
        unsigned long long* __restrict__ o =
            reinterpret_cast<unsigned long long*>(
                out + (tileBase + tid + (size_t)j * BLOCK) * OUT_DIM);
#pragma unroll
        for (int p = 0; p < 5; ++p)
            __stcs(o + p, (unsigned long long)acc[j][p]);
    }
}

extern "C" void kernel_launch(void* const* d_in, const int* in_sizes, int n_in,
                              void* d_out, int out_size) {
    const float* x = (const float*)d_in[0];  // [BATCH, 64]
    const float* W = (const float*)d_in[1];  // [64, 10] row-major
    float* out = (float*)d_out;              // [BATCH, 10]

    static int configured = 0;
    if (!configured) {
        cudaFuncSetAttribute(neat_matmul_kernel,
                             cudaFuncAttributeMaxDynamicSharedMemorySize,
                             SMEM_TOTAL);
        configured = 1;
    }

    const int grid = BATCH / TILE_ROWS;  // 2048, exact
    neat_matmul_kernel<<<grid, BLOCK, SMEM_TOTAL>>>(x, W, out);
}